// round 14
// baseline (speedup 1.0000x reference)
#include <cuda_runtime.h>
#include <cuda_bf16.h>
#include <math.h>

#define Bsz 64
#define TT 512
#define DD 512
#define HH 512
#define G4 2048   // 4*H
#define NCTA 128
#define NCTA_DIR 64
#define CLSZ 8

// Scratch (static device globals are the sanctioned scratch mechanism)
__device__ float g_xz[2][TT][G4][Bsz];      // [dir][t][gatecol][b]  (512 MB)
// h state as separate hi/mid bf16 planes, kpair rows PADDED to pitch 72 so the
// global layout is byte-identical to the SMEM chunk layout (1D bulk copies).
__device__ unsigned g_hpl[2][2][2][256][72];
__device__ unsigned g_cnt2[2][32];            // per-direction heavyweight barrier
__device__ volatile unsigned g_phase2[2][32];
__device__ unsigned g_flag[2][64][32];        // distributed step flags (128B stride)

// ---------------------------------------------------------------------------
// helpers
// ---------------------------------------------------------------------------
__device__ __forceinline__ unsigned f2tf(float f) {
    unsigned r;
    asm("cvt.rna.tf32.f32 %0, %1;" : "=r"(r) : "f"(f));
    return r;
}

__device__ __forceinline__ void mma1688(float c[4],
                                        unsigned a0, unsigned a1, unsigned a2, unsigned a3,
                                        unsigned b0, unsigned b1) {
    asm volatile(
        "mma.sync.aligned.m16n8k8.row.col.f32.tf32.tf32.f32 "
        "{%0,%1,%2,%3}, {%4,%5,%6,%7}, {%8,%9}, {%0,%1,%2,%3};\n"
        : "+f"(c[0]), "+f"(c[1]), "+f"(c[2]), "+f"(c[3])
        : "r"(a0), "r"(a1), "r"(a2), "r"(a3), "r"(b0), "r"(b1));
}

__device__ __forceinline__ void mma16816(float c[4],
                                         unsigned a0, unsigned a1, unsigned a2, unsigned a3,
                                         unsigned b0, unsigned b1) {
    asm volatile(
        "mma.sync.aligned.m16n8k16.row.col.f32.bf16.bf16.f32 "
        "{%0,%1,%2,%3}, {%4,%5,%6,%7}, {%8,%9}, {%0,%1,%2,%3};\n"
        : "+f"(c[0]), "+f"(c[1]), "+f"(c[2]), "+f"(c[3])
        : "r"(a0), "r"(a1), "r"(a2), "r"(a3), "r"(b0), "r"(b1));
}

__device__ __forceinline__ unsigned prmt(unsigned a, unsigned b, unsigned sel) {
    unsigned d;
    asm("prmt.b32 %0, %1, %2, %3;" : "=r"(d) : "r"(a), "r"(b), "r"(sel));
    return d;
}

__device__ __forceinline__ void cp16(unsigned saddr, const void* g) {
    asm volatile("cp.async.cg.shared.global [%0], [%1], 16;" :: "r"(saddr), "l"(g));
}
__device__ __forceinline__ void cp_commit() {
    asm volatile("cp.async.commit_group;");
}
template <int N>
__device__ __forceinline__ void cp_wait() {
    asm volatile("cp.async.wait_group %0;" :: "n"(N));
}

// bf16 split: w = hi + mid (+ eps); returns packed (mid<<16 | hi)
__device__ __forceinline__ unsigned bf16_split_pack(float w) {
    __nv_bfloat16 bh = __float2bfloat16(w);
    float mid = w - __bfloat162float(bh);
    __nv_bfloat16 bm = __float2bfloat16(mid);
    return ((unsigned)__bfloat16_as_ushort(bm) << 16) |
           (unsigned)__bfloat16_as_ushort(bh);
}

// release/acquire primitives
__device__ __forceinline__ void st_release(unsigned* p, unsigned v) {
    asm volatile("st.release.gpu.global.u32 [%0], %1;"
                 :: "l"(p), "r"(v) : "memory");
}
__device__ __forceinline__ unsigned ld_acquire(unsigned* p) {
    unsigned v;
    asm volatile("ld.acquire.gpu.global.u32 %0, [%1];"
                 : "=r"(v) : "l"(p) : "memory");
    return v;
}

// mbarrier primitives
__device__ __forceinline__ void mbar_init(unsigned mb, unsigned count) {
    asm volatile("mbarrier.init.shared.b64 [%0], %1;"
                 :: "r"(mb), "r"(count) : "memory");
}
__device__ __forceinline__ void mbar_expect_tx(unsigned mb, unsigned bytes) {
    asm volatile("mbarrier.arrive.expect_tx.shared.b64 _, [%0], %1;"
                 :: "r"(mb), "r"(bytes) : "memory");
}
__device__ __forceinline__ void mbar_wait(unsigned mb, unsigned parity) {
    asm volatile(
        "{\n\t"
        ".reg .pred P%=;\n\t"
        "WAIT%=:\n\t"
        "mbarrier.try_wait.parity.acquire.cta.shared::cta.b64 P%=, [%0], %1, 0x989680;\n\t"
        "@P%= bra.uni DONE%=;\n\t"
        "bra.uni WAIT%=;\n\t"
        "DONE%=:\n\t"
        "}"
        :: "r"(mb), "r"(parity) : "memory");
}
__device__ __forceinline__ void bulk_mcast(unsigned dst, const void* src,
                                           unsigned bytes, unsigned mb,
                                           unsigned short mask) {
    asm volatile(
        "cp.async.bulk.shared::cluster.global.mbarrier::complete_tx::bytes"
        ".multicast::cluster [%0], [%1], %2, [%3], %4;"
        :: "r"(dst), "l"(src), "r"(bytes), "r"(mb), "h"(mask) : "memory");
}

// ---------------------------------------------------------------------------
// Kernel 1: input projection via tf32 tensor-core MMA (unchanged from R2).
// ---------------------------------------------------------------------------
#define W_PITCH 264
#define X_PITCH 36
#define W_ELEMS (32 * W_PITCH)
#define X_ELEMS (64 * X_PITCH)
#define PROJ_SMEM ((W_ELEMS + 2 * X_ELEMS) * 4)

__global__ __launch_bounds__(512, 1) void proj_mma_kernel(
    const float* __restrict__ x,
    const float* __restrict__ Wfk, const float* __restrict__ bf,
    const float* __restrict__ Wbk, const float* __restrict__ bb)
{
    extern __shared__ unsigned psm[];
    unsigned* w_s = psm;                 // [32][W_PITCH]  (k x col)
    unsigned* x_s = psm + W_ELEMS;       // [2][64][X_PITCH] (ts x b x k)

    const int tid = threadIdx.x;
    const int colTile = blockIdx.x;      // 0..7
    const int tpair = blockIdx.y;        // 0..255
    const int dir = blockIdx.z;          // 0..1
    const int colbase = colTile * 256;
    const float* __restrict__ Wk = dir ? Wbk : Wfk;
    const float* __restrict__ bias = dir ? bb : bf;

    const int lane = tid & 31;
    const int grp = lane >> 2;
    const int tig = lane & 3;
    const int wid = tid >> 5;
    const int wn = wid & 1;
    const int wm = wid >> 1;

    float acc[2][2][4][4];
    #pragma unroll
    for (int a = 0; a < 2; a++)
        #pragma unroll
        for (int b = 0; b < 2; b++)
            #pragma unroll
            for (int c = 0; c < 4; c++)
                #pragma unroll
                for (int d = 0; d < 4; d++) acc[a][b][c][d] = 0.f;

    #pragma unroll 1
    for (int k0 = 0; k0 < DD; k0 += 32) {
        __syncthreads();
        #pragma unroll
        for (int j = 0; j < 4; j++) {
            int e4 = tid + j * 512;
            int kk = e4 >> 6;
            int cc = (e4 & 63) * 4;
            float4 v = *(const float4*)(Wk + (size_t)(k0 + kk) * G4 + colbase + cc);
            uint4 u = make_uint4(f2tf(v.x), f2tf(v.y), f2tf(v.z), f2tf(v.w));
            *(uint4*)(w_s + kk * W_PITCH + cc) = u;
        }
        #pragma unroll
        for (int j = 0; j < 2; j++) {
            int f4 = tid + j * 512;
            int ts = f4 >> 9;
            int r = f4 & 511;
            int b = r >> 3;
            int kc4 = (r & 7) * 4;
            int t = tpair * 2 + ts;
            float4 v = *(const float4*)(x + ((size_t)b * TT + t) * DD + k0 + kc4);
            uint4 u = make_uint4(f2tf(v.x), f2tf(v.y), f2tf(v.z), f2tf(v.w));
            *(uint4*)(x_s + ts * X_ELEMS + b * X_PITCH + kc4) = u;
        }
        __syncthreads();

        #pragma unroll
        for (int ks = 0; ks < 4; ks++) {
            const int kr = ks * 8;
            unsigned a[2][4];
            #pragma unroll
            for (int mt = 0; mt < 2; mt++) {
                int cb = wm * 32 + mt * 16 + grp;
                a[mt][0] = w_s[(kr + tig) * W_PITCH + cb];
                a[mt][1] = w_s[(kr + tig) * W_PITCH + cb + 8];
                a[mt][2] = w_s[(kr + tig + 4) * W_PITCH + cb];
                a[mt][3] = w_s[(kr + tig + 4) * W_PITCH + cb + 8];
            }
            unsigned bb_[2][4][2];
            #pragma unroll
            for (int ts = 0; ts < 2; ts++)
                #pragma unroll
                for (int nt = 0; nt < 4; nt++) {
                    int idx = ts * X_ELEMS + (wn * 32 + nt * 8 + grp) * X_PITCH + kr + tig;
                    bb_[ts][nt][0] = x_s[idx];
                    bb_[ts][nt][1] = x_s[idx + 4];
                }
            #pragma unroll
            for (int ts = 0; ts < 2; ts++)
                #pragma unroll
                for (int mt = 0; mt < 2; mt++)
                    #pragma unroll
                    for (int nt = 0; nt < 4; nt++)
                        mma1688(acc[ts][mt][nt],
                                a[mt][0], a[mt][1], a[mt][2], a[mt][3],
                                bb_[ts][nt][0], bb_[ts][nt][1]);
        }
    }

    #pragma unroll
    for (int ts = 0; ts < 2; ts++) {
        int t = tpair * 2 + ts;
        float* gx = &g_xz[dir][t][0][0];
        #pragma unroll
        for (int mt = 0; mt < 2; mt++) {
            int col = colbase + wm * 32 + mt * 16 + grp;
            float bv = bias[col];
            float bv8 = bias[col + 8];
            #pragma unroll
            for (int nt = 0; nt < 4; nt++) {
                int b = wn * 32 + nt * 8 + tig * 2;
                float2 lo = make_float2(acc[ts][mt][nt][0] + bv,
                                        acc[ts][mt][nt][1] + bv);
                float2 hi = make_float2(acc[ts][mt][nt][2] + bv8,
                                        acc[ts][mt][nt][3] + bv8);
                *(float2*)(gx + (size_t)col * Bsz + b) = lo;
                *(float2*)(gx + (size_t)(col + 8) * Bsz + b) = hi;
            }
        }
    }
}

// ---------------------------------------------------------------------------
// Kernel 2: persistent bidirectional LSTM scan.
// R14 = R13 compute core + 8-CTA clusters with cp.async.bulk MULTICAST
// cooperative h staging (L2 h-traffic /4, LSU freed, mbarrier completion).
// ---------------------------------------------------------------------------
__device__ __forceinline__ float sigf(float v) { return 1.f / (1.f + __expf(-v)); }

// Wpack: [term(hi=0,mid=1)][wm(2)][kstep16(32)][lane(32)][4]  (uint32 words)
#define WPK_TERM (2 * 32 * 32 * 4)   // 8192 words per term
#define WPK_TOTAL (2 * WPK_TERM)     // 16384 words (64 KB)
#define HPW 72                       // words per kpair row (72 mod 32 == 8)
#define PLW (64 * HPW)               // 4608 words per plane per chunk
#define CHUNKW (2 * PLW)             // 9216 words per chunk buffer
#define PSTRIDE (256 * HPW)          // plane stride in global (18432 words)
#define CHUNK_BYTES (CHUNKW * 4)     // 36864
#define SLICE_BYTES (8 * HPW * 4)    // 2304 per rank per plane
// SMEM words: Wpack 16384, hs 4*9216, zx 2*2048, mbar 16 = 57360 (229440 B)
#define ZX_OFF (WPK_TOTAL + 4 * CHUNKW)
#define MBAR_OFF (ZX_OFF + 2 * 2048)
#define SCAN_SMEM ((MBAR_OFF + 16) * 4)

__global__ __launch_bounds__(256, 1) __cluster_dims__(CLSZ, 1, 1)
void scan_mma_kernel(
    const float* __restrict__ Wfr, const float* __restrict__ Wbr,
    float* __restrict__ out)
{
    extern __shared__ unsigned usmem[];
    unsigned* Wpack = usmem;                     // fragment-packed bf16x2 hi/mid
    unsigned* hs = usmem + WPK_TOTAL;            // [4][2 plane][64 kpair][HPW]
    float* zx  = (float*)(usmem + ZX_OFF);       // [2][32][64]
    float* zbuf = (float*)(usmem + WPK_TOTAL + CHUNKW);  // alias: buffer 1

    const int tx = threadIdx.x;
    const int cta = blockIdx.x;        // 0..127
    const int dir = cta >> 6;
    const int ci = cta & 63;           // index within direction
    const int rank = ci & (CLSZ - 1);  // cluster rank
    const int hbase = ci * 8;
    const float* __restrict__ Wr = dir ? Wbr : Wfr;

    // Pre-split + fragment-pack resident Wr slice as bf16x2 words.
    for (int e = tx; e < WPK_TERM; e += 256) {
        int j = e & 3;
        int lane_ = (e >> 2) & 31;
        int kstep = (e >> 7) & 31;
        int wmi = e >> 12;
        int g_ = lane_ >> 2, t_ = lane_ & 3;
        int m = wmi * 16 + g_ + ((j & 1) ? 8 : 0);
        int kb = kstep * 16 + 2 * t_ + ((j & 2) ? 8 : 0);
        int gate = m >> 3, jc = m & 7;
        float w0 = Wr[(size_t)kb * G4 + gate * HH + hbase + jc];
        float w1 = Wr[(size_t)(kb + 1) * G4 + gate * HH + hbase + jc];
        unsigned p0 = bf16_split_pack(w0);   // (mid<<16)|hi
        unsigned p1 = bf16_split_pack(w1);
        Wpack[e] = prmt(p0, p1, 0x5410);                // hi word {hi0,hi1}
        Wpack[WPK_TERM + e] = prmt(p0, p1, 0x7632);     // mid word {mid0,mid1}
    }

    // Zero our slice of h plane buffer 0 (4 kpairs x 64 b x 2 planes)
    for (int idx = tx; idx < 512; idx += 256) {
        int pl = idx >> 8;
        int r = idx & 255;
        int kp = (hbase >> 1) + (r >> 6);
        int b = r & 63;
        g_hpl[0][dir][pl][kp][b] = 0u;
    }

    // Warp layout for MMA
    const int lane = tx & 31;
    const int warp = tx >> 5;
    const int wm = warp >> 2;          // 0..1, m0 = wm*16
    const int n0 = (warp & 3) * 16;    // n (batch) base
    const int grp = lane >> 2;         // 0..7
    const int tig = lane & 3;          // 0..3

    // Gate-phase mapping: thread owns adjacent pair (hj0, hj0+1) for batch b_p
    const int b_p = tx & 63;
    const int hj0 = (tx >> 6) * 2;     // 0,2,4,6
    const int hj1 = hj0 + 1;
    float c_reg0 = 0.f, c_reg1 = 0.f;

    const unsigned smem_u32 = (unsigned)__cvta_generic_to_shared(usmem);
    const unsigned hs_addr = smem_u32 + WPK_TOTAL * 4;
    const unsigned zx_addr = smem_u32 + ZX_OFF * 4;
    const unsigned mbar_addr = smem_u32 + MBAR_OFF * 4;

    float* out_sent = out + (size_t)Bsz * TT * (2 * HH);
    unsigned* cntp = &g_cnt2[dir][0];
    volatile unsigned* php = &g_phase2[dir][0];

    // mbarrier init (count 1: the per-step expect_tx arrive)
    if (tx == 0) {
        #pragma unroll
        for (int c = 0; c < 4; c++) mbar_init(mbar_addr + c * 8, 1);
        asm volatile("fence.proxy.async.shared::cta;" ::: "memory");
    }
    __syncthreads();
    // cluster barrier: peers' mbarrier inits visible before any multicast
    asm volatile("barrier.cluster.arrive.aligned;" ::: "memory");
    asm volatile("barrier.cluster.wait.aligned;" ::: "memory");

    // Global init barrier (one-time heavyweight; phase 0 -> 1)
    if (tx == 0) {
        __threadfence();
        unsigned old = atomicAdd(cntp, 1u);
        if (old == NCTA_DIR - 1) { *cntp = 0; __threadfence(); *php = 1; }
        else { while (*php < 1u) { } }
        __threadfence();
    }
    __syncthreads();

    // Prefetch zx[t=0] into buffer 0 (its own cp.async group)
    {
        const float* xzb = &g_xz[dir][dir ? (TT - 1) : 0][0][0];
        #pragma unroll
        for (int i = 0; i < 2; i++) {
            int s = tx + i * 256;
            int c = s >> 4, off = (s & 15) * 4;
            int gate = c >> 3, jj = c & 7;
            cp16(zx_addr + (c * 64 + off) * 4,
                 xzb + (size_t)(gate * HH + hbase + jj) * Bsz + off);
        }
        cp_commit();
    }

    for (int t = 0; t < TT; t++) {
        const int rb = t & 1, wb = (t + 1) & 1;
        const int tq = dir ? (TT - 1 - t) : t;
        const int zb = t & 1;
        const unsigned par = (unsigned)(t & 1);
        const unsigned* hsrc = &g_hpl[rb][dir][0][0][0];   // padded planes

        // Issue cooperative multicast slices for all 4 chunks (thread 0)
        if (tx == 0) {
            #pragma unroll
            for (int c = 0; c < 4; c++) {
                unsigned mb = mbar_addr + c * 8;
                mbar_expect_tx(mb, CHUNK_BYTES);
                #pragma unroll
                for (int pl = 0; pl < 2; pl++) {
                    const unsigned* src =
                        hsrc + pl * PSTRIDE + (c * 64 + rank * 8) * HPW;
                    unsigned dst = hs_addr +
                        (c * CHUNKW + pl * PLW + rank * 8 * HPW) * 4;
                    bulk_mcast(dst, src, SLICE_BYTES, mb, (unsigned short)0xFF);
                }
            }
        }
        // zx prefetch for t+1 (cp.async, all threads)
        if (t < TT - 1) {
            const int tq2 = dir ? (TT - 2 - t) : (t + 1);
            const float* xzb = &g_xz[dir][tq2][0][0];
            unsigned zdst = zx_addr + ((t + 1) & 1) * 2048 * 4;
            #pragma unroll
            for (int i = 0; i < 2; i++) {
                int s = tx + i * 256;
                int c = s >> 4, off = (s & 15) * 4;
                int gate = c >> 3, jj = c & 7;
                cp16(zdst + (c * 64 + off) * 4,
                     xzb + (size_t)(gate * HH + hbase + jj) * Bsz + off);
            }
            cp_commit();
        }

        float acc[2][4];
        #pragma unroll
        for (int nt = 0; nt < 2; nt++)
            #pragma unroll
            for (int d = 0; d < 4; d++) acc[nt][d] = 0.f;

        #pragma unroll 1
        for (int ch = 0; ch < 4; ch++) {
            mbar_wait(mbar_addr + ch * 8, par);   // per-thread; warps may skew
            const unsigned* hcH = hs + ch * CHUNKW;
            const unsigned* hcM = hcH + PLW;
            const unsigned* WH = Wpack + (wm * 32 + ch * 8) * 128;
            const unsigned* WM = WH + WPK_TERM;

            #pragma unroll
            for (int ks = 0; ks < 8; ks++) {            // 8 k16-steps per chunk
                uint4 AH = *(const uint4*)(WH + ks * 128 + lane * 4);
                uint4 AM = *(const uint4*)(WM + ks * 128 + lane * 4);
                const int kpb = ks * 8 + tig;
                #pragma unroll
                for (int nt = 0; nt < 2; nt++) {
                    int n = n0 + nt * 8 + grp;
                    unsigned bh0 = hcH[kpb * HPW + n];
                    unsigned bh1 = hcH[(kpb + 4) * HPW + n];
                    unsigned bm0 = hcM[kpb * HPW + n];
                    unsigned bm1 = hcM[(kpb + 4) * HPW + n];
                    mma16816(acc[nt], AH.x, AH.y, AH.z, AH.w, bh0, bh1);
                    mma16816(acc[nt], AM.x, AM.y, AM.z, AM.w, bh0, bh1);
                    mma16816(acc[nt], AH.x, AH.y, AH.z, AH.w, bm0, bm1);
                }
            }
        }

        cp_wait<0>();        // zx(t+1) long since arrived
        __syncthreads();     // all warps done with buffer 1 before zbuf alias

        // Write acc into zbuf[c][b]  (c = m index = gate*8+j)
        {
            int m0 = wm * 16;
            #pragma unroll
            for (int nt = 0; nt < 2; nt++) {
                int n = n0 + nt * 8 + tig * 2;
                *(float2*)&zbuf[(m0 + grp) * 64 + n] =
                    make_float2(acc[nt][0], acc[nt][1]);
                *(float2*)&zbuf[(m0 + grp + 8) * 64 + n] =
                    make_float2(acc[nt][2], acc[nt][3]);
            }
        }
        __syncthreads();

        // Gate phase: (hj0, b_p) and (hj0+1, b_p)
        const float* zxc = zx + zb * 2048;
        float z0[4], z1[4];
        #pragma unroll
        for (int gate = 0; gate < 4; gate++) {
            int c0i = (gate * 8 + hj0) * 64 + b_p;
            int c1i = (gate * 8 + hj1) * 64 + b_p;
            z0[gate] = zxc[c0i] + zbuf[c0i];
            z1[gate] = zxc[c1i] + zbuf[c1i];
        }
        float i0 = sigf(z0[0]), f0 = sigf(z0[1]), g0 = tanhf(z0[2]), o0 = sigf(z0[3]);
        c_reg0 = f0 * c_reg0 + i0 * g0;
        float h0v = o0 * tanhf(c_reg0);
        float i1 = sigf(z1[0]), f1 = sigf(z1[1]), g1 = tanhf(z1[2]), o1 = sigf(z1[3]);
        c_reg1 = f1 * c_reg1 + i1 * g1;
        float h1v = o1 * tanhf(c_reg1);

        // Publish split h: adjacent (even,odd) pair -> one word per plane
        {
            unsigned p0 = bf16_split_pack(h0v);
            unsigned p1 = bf16_split_pack(h1v);
            int kp = (hbase >> 1) + (tx >> 6);
            g_hpl[wb][dir][0][kp][b_p] = prmt(p0, p1, 0x5410);  // hi plane word
            g_hpl[wb][dir][1][kp][b_p] = prmt(p0, p1, 0x7632);  // mid plane word
        }

        size_t wo = ((size_t)b_p * TT + tq) * (2 * HH) + dir * HH + hbase + hj0;
        if (t < TT - 1) {
            // ---- distributed-flag arrive (release; cumulative over block) ----
            __syncthreads();
            if (tx == 0) st_release(&g_flag[dir][ci][0], (unsigned)(t + 2));
            // ---- output store overlaps the poll ----
            *(float2*)(out + wo) = make_float2(h0v, h1v);
            // ---- parallel poll: thread i watches flag slot i ----
            const unsigned target = (unsigned)(t + 2);
            int done;
            do {
                unsigned v = (tx < NCTA_DIR) ? ld_acquire(&g_flag[dir][tx][0])
                                             : target;
                done = __syncthreads_and((int)(v >= target));
            } while (!done);
        } else {
            *(float2*)(out + wo) = make_float2(h0v, h1v);
            size_t so = (size_t)b_p * (2 * HH) + dir * HH + hbase + hj0;
            *(float2*)(out_sent + so) = make_float2(h0v, h1v);
        }
    }

    // ---- endgame: full heavyweight barrier (all polls done), then reset ----
    __syncthreads();
    if (tx == 0) {
        __threadfence();
        unsigned old = atomicAdd(cntp, 1u);
        if (old == NCTA_DIR - 1) { *cntp = 0; __threadfence(); *php = 2; }
        else { while (*php < 2u) { } }
        __threadfence();
        // safe now: every CTA has passed every flag poll
        g_flag[dir][ci][0] = 0u;
        __threadfence();
        unsigned old2 = atomicAdd(cntp, 1u);
        if (old2 == NCTA_DIR - 1) {      // last one restores barrier state
            *cntp = 0;
            __threadfence();
            *php = 0;
        }
    }
}

// ---------------------------------------------------------------------------
extern "C" void kernel_launch(void* const* d_in, const int* in_sizes, int n_in,
                              void* d_out, int out_size) {
    const float* x   = (const float*)d_in[0];
    const float* Wfk = (const float*)d_in[1];
    const float* Wfr = (const float*)d_in[2];
    const float* bf  = (const float*)d_in[3];
    const float* Wbk = (const float*)d_in[4];
    const float* Wbr = (const float*)d_in[5];
    const float* bb  = (const float*)d_in[6];
    float* out = (float*)d_out;

    cudaFuncSetAttribute(scan_mma_kernel,
                         cudaFuncAttributeMaxDynamicSharedMemorySize, SCAN_SMEM);
    cudaFuncSetAttribute(proj_mma_kernel,
                         cudaFuncAttributeMaxDynamicSharedMemorySize, PROJ_SMEM);

    dim3 pg(8, 256, 2);
    proj_mma_kernel<<<pg, 512, PROJ_SMEM>>>(x, Wfk, bf, Wbk, bb);
    scan_mma_kernel<<<NCTA, 256, SCAN_SMEM>>>(Wfr, Wbr, out);
}

// round 16
// speedup vs baseline: 1.5261x; 1.5261x over previous
#include <cuda_runtime.h>
#include <cuda_bf16.h>
#include <math.h>

#define Bsz 64
#define TT 512
#define DD 512
#define HH 512
#define G4 2048   // 4*H
#define NCTA 128
#define NCTA_DIR 64

// Scratch (static device globals are the sanctioned scratch mechanism)
__device__ float g_xz[2][TT][G4][Bsz];      // [dir][t][gatecol][b]  (512 MB)
// h state as separate hi/mid bf16 planes, kpair-packed:
// word [buf][dir][plane][kpair][b] = (bf16(k_even) | bf16(k_odd)<<16)
__device__ unsigned g_hpl[2][2][2][256][64];
__device__ unsigned g_cnt2[2][32];            // per-direction heavyweight barrier
__device__ volatile unsigned g_phase2[2][32];
__device__ unsigned g_flag[2][64][32];        // distributed step flags (128B stride)

// ---------------------------------------------------------------------------
// helpers
// ---------------------------------------------------------------------------
__device__ __forceinline__ unsigned f2tf(float f) {
    unsigned r;
    asm("cvt.rna.tf32.f32 %0, %1;" : "=r"(r) : "f"(f));
    return r;
}

__device__ __forceinline__ void mma1688(float c[4],
                                        unsigned a0, unsigned a1, unsigned a2, unsigned a3,
                                        unsigned b0, unsigned b1) {
    asm volatile(
        "mma.sync.aligned.m16n8k8.row.col.f32.tf32.tf32.f32 "
        "{%0,%1,%2,%3}, {%4,%5,%6,%7}, {%8,%9}, {%0,%1,%2,%3};\n"
        : "+f"(c[0]), "+f"(c[1]), "+f"(c[2]), "+f"(c[3])
        : "r"(a0), "r"(a1), "r"(a2), "r"(a3), "r"(b0), "r"(b1));
}

__device__ __forceinline__ void mma16816(float c[4],
                                         unsigned a0, unsigned a1, unsigned a2, unsigned a3,
                                         unsigned b0, unsigned b1) {
    asm volatile(
        "mma.sync.aligned.m16n8k16.row.col.f32.bf16.bf16.f32 "
        "{%0,%1,%2,%3}, {%4,%5,%6,%7}, {%8,%9}, {%0,%1,%2,%3};\n"
        : "+f"(c[0]), "+f"(c[1]), "+f"(c[2]), "+f"(c[3])
        : "r"(a0), "r"(a1), "r"(a2), "r"(a3), "r"(b0), "r"(b1));
}

__device__ __forceinline__ unsigned prmt(unsigned a, unsigned b, unsigned sel) {
    unsigned d;
    asm("prmt.b32 %0, %1, %2, %3;" : "=r"(d) : "r"(a), "r"(b), "r"(sel));
    return d;
}

__device__ __forceinline__ void cp16(unsigned saddr, const void* g) {
    asm volatile("cp.async.cg.shared.global [%0], [%1], 16;" :: "r"(saddr), "l"(g));
}
__device__ __forceinline__ void cp_commit() {
    asm volatile("cp.async.commit_group;");
}
template <int N>
__device__ __forceinline__ void cp_wait() {
    asm volatile("cp.async.wait_group %0;" :: "n"(N));
}

// bf16 split: w = hi + mid (+ eps); returns packed (mid<<16 | hi)
__device__ __forceinline__ unsigned bf16_split_pack(float w) {
    __nv_bfloat16 bh = __float2bfloat16(w);
    float mid = w - __bfloat162float(bh);
    __nv_bfloat16 bm = __float2bfloat16(mid);
    return ((unsigned)__bfloat16_as_ushort(bm) << 16) |
           (unsigned)__bfloat16_as_ushort(bh);
}

// release/acquire primitives
__device__ __forceinline__ void st_release(unsigned* p, unsigned v) {
    asm volatile("st.release.gpu.global.u32 [%0], %1;"
                 :: "l"(p), "r"(v) : "memory");
}
__device__ __forceinline__ unsigned ld_acquire(unsigned* p) {
    unsigned v;
    asm volatile("ld.acquire.gpu.global.u32 %0, [%1];"
                 : "=r"(v) : "l"(p) : "memory");
    return v;
}

// ---------------------------------------------------------------------------
// Kernel 1: input projection via tf32 tensor-core MMA (unchanged from R2).
// ---------------------------------------------------------------------------
#define W_PITCH 264
#define X_PITCH 36
#define W_ELEMS (32 * W_PITCH)
#define X_ELEMS (64 * X_PITCH)
#define PROJ_SMEM ((W_ELEMS + 2 * X_ELEMS) * 4)

__global__ __launch_bounds__(512, 1) void proj_mma_kernel(
    const float* __restrict__ x,
    const float* __restrict__ Wfk, const float* __restrict__ bf,
    const float* __restrict__ Wbk, const float* __restrict__ bb)
{
    extern __shared__ unsigned psm[];
    unsigned* w_s = psm;                 // [32][W_PITCH]  (k x col)
    unsigned* x_s = psm + W_ELEMS;       // [2][64][X_PITCH] (ts x b x k)

    const int tid = threadIdx.x;
    const int colTile = blockIdx.x;      // 0..7
    const int tpair = blockIdx.y;        // 0..255
    const int dir = blockIdx.z;          // 0..1
    const int colbase = colTile * 256;
    const float* __restrict__ Wk = dir ? Wbk : Wfk;
    const float* __restrict__ bias = dir ? bb : bf;

    const int lane = tid & 31;
    const int grp = lane >> 2;
    const int tig = lane & 3;
    const int wid = tid >> 5;
    const int wn = wid & 1;
    const int wm = wid >> 1;

    float acc[2][2][4][4];
    #pragma unroll
    for (int a = 0; a < 2; a++)
        #pragma unroll
        for (int b = 0; b < 2; b++)
            #pragma unroll
            for (int c = 0; c < 4; c++)
                #pragma unroll
                for (int d = 0; d < 4; d++) acc[a][b][c][d] = 0.f;

    #pragma unroll 1
    for (int k0 = 0; k0 < DD; k0 += 32) {
        __syncthreads();
        #pragma unroll
        for (int j = 0; j < 4; j++) {
            int e4 = tid + j * 512;
            int kk = e4 >> 6;
            int cc = (e4 & 63) * 4;
            float4 v = *(const float4*)(Wk + (size_t)(k0 + kk) * G4 + colbase + cc);
            uint4 u = make_uint4(f2tf(v.x), f2tf(v.y), f2tf(v.z), f2tf(v.w));
            *(uint4*)(w_s + kk * W_PITCH + cc) = u;
        }
        #pragma unroll
        for (int j = 0; j < 2; j++) {
            int f4 = tid + j * 512;
            int ts = f4 >> 9;
            int r = f4 & 511;
            int b = r >> 3;
            int kc4 = (r & 7) * 4;
            int t = tpair * 2 + ts;
            float4 v = *(const float4*)(x + ((size_t)b * TT + t) * DD + k0 + kc4);
            uint4 u = make_uint4(f2tf(v.x), f2tf(v.y), f2tf(v.z), f2tf(v.w));
            *(uint4*)(x_s + ts * X_ELEMS + b * X_PITCH + kc4) = u;
        }
        __syncthreads();

        #pragma unroll
        for (int ks = 0; ks < 4; ks++) {
            const int kr = ks * 8;
            unsigned a[2][4];
            #pragma unroll
            for (int mt = 0; mt < 2; mt++) {
                int cb = wm * 32 + mt * 16 + grp;
                a[mt][0] = w_s[(kr + tig) * W_PITCH + cb];
                a[mt][1] = w_s[(kr + tig) * W_PITCH + cb + 8];
                a[mt][2] = w_s[(kr + tig + 4) * W_PITCH + cb];
                a[mt][3] = w_s[(kr + tig + 4) * W_PITCH + cb + 8];
            }
            unsigned bb_[2][4][2];
            #pragma unroll
            for (int ts = 0; ts < 2; ts++)
                #pragma unroll
                for (int nt = 0; nt < 4; nt++) {
                    int idx = ts * X_ELEMS + (wn * 32 + nt * 8 + grp) * X_PITCH + kr + tig;
                    bb_[ts][nt][0] = x_s[idx];
                    bb_[ts][nt][1] = x_s[idx + 4];
                }
            #pragma unroll
            for (int ts = 0; ts < 2; ts++)
                #pragma unroll
                for (int mt = 0; mt < 2; mt++)
                    #pragma unroll
                    for (int nt = 0; nt < 4; nt++)
                        mma1688(acc[ts][mt][nt],
                                a[mt][0], a[mt][1], a[mt][2], a[mt][3],
                                bb_[ts][nt][0], bb_[ts][nt][1]);
        }
    }

    #pragma unroll
    for (int ts = 0; ts < 2; ts++) {
        int t = tpair * 2 + ts;
        float* gx = &g_xz[dir][t][0][0];
        #pragma unroll
        for (int mt = 0; mt < 2; mt++) {
            int col = colbase + wm * 32 + mt * 16 + grp;
            float bv = bias[col];
            float bv8 = bias[col + 8];
            #pragma unroll
            for (int nt = 0; nt < 4; nt++) {
                int b = wn * 32 + nt * 8 + tig * 2;
                float2 lo = make_float2(acc[ts][mt][nt][0] + bv,
                                        acc[ts][mt][nt][1] + bv);
                float2 hi = make_float2(acc[ts][mt][nt][2] + bv8,
                                        acc[ts][mt][nt][3] + bv8);
                *(float2*)(gx + (size_t)col * Bsz + b) = lo;
                *(float2*)(gx + (size_t)(col + 8) * Bsz + b) = hi;
            }
        }
    }
}

// ---------------------------------------------------------------------------
// Kernel 2: persistent bidirectional LSTM scan.
// R15 = R13 + producer-group polling (chunk ch waits only on its 16 producer
// CTAs, interleaved with compute) + 4 up-front chunk buffers (no refill).
// ---------------------------------------------------------------------------
__device__ __forceinline__ float sigf(float v) { return 1.f / (1.f + __expf(-v)); }

// Wpack: [term(hi=0,mid=1)][wm(2)][kstep16(32)][lane(32)][4]  (uint32 words)
#define WPK_TERM (2 * 32 * 32 * 4)   // 8192 words per term
#define WPK_TOTAL (2 * WPK_TERM)     // 16384 words (64 KB)
#define HPW 72                       // words per kpair row (72 mod 32 == 8)
#define PLW (64 * HPW)               // 4608 words per plane per chunk
#define CHUNKW (2 * PLW)             // 9216 words per chunk buffer
// SMEM words: Wpack 16384, hs 4*9216 (zbuf aliases buf0), zx 2*2048 = 57344
#define SCAN_SMEM ((WPK_TOTAL + 4 * CHUNKW + 2 * 2048) * 4)   // 229376 B

__device__ __forceinline__ void poll_group(unsigned* flags, int g, int tx,
                                           unsigned target) {
    int done;
    do {
        unsigned v = (tx < 16) ? ld_acquire(flags + (g * 16 + tx) * 32) : target;
        done = __syncthreads_and((int)(v >= target));
    } while (!done);
}

__device__ __forceinline__ void issue_chunk(unsigned hs_addr,
                                            const unsigned* hsrc,
                                            int ch, int tx) {
    unsigned dstb = hs_addr + ch * CHUNKW * 4;
    #pragma unroll
    for (int i = 0; i < 8; i++) {
        int f4 = tx + i * 256;               // 0..2047
        int pl = f4 >> 10;                   // 0..1
        int kpl = (f4 >> 4) & 63;            // 0..63
        int b4 = (f4 & 15) * 4;              // 0..60
        cp16(dstb + (pl * PLW + kpl * HPW + b4) * 4,
             hsrc + pl * 16384 + (ch * 64 + kpl) * 64 + b4);
    }
}

__device__ __forceinline__ void compute_chunk(float acc[2][4],
                                              const unsigned* hs,
                                              const unsigned* Wpack,
                                              int ch, int wm, int lane,
                                              int tig, int grp, int n0) {
    const unsigned* hcH = hs + ch * CHUNKW;
    const unsigned* hcM = hcH + PLW;
    const unsigned* WH = Wpack + (wm * 32 + ch * 8) * 128;
    const unsigned* WM = WH + WPK_TERM;
    #pragma unroll
    for (int ks = 0; ks < 8; ks++) {
        uint4 AH = *(const uint4*)(WH + ks * 128 + lane * 4);
        uint4 AM = *(const uint4*)(WM + ks * 128 + lane * 4);
        const int kpb = ks * 8 + tig;
        #pragma unroll
        for (int nt = 0; nt < 2; nt++) {
            int n = n0 + nt * 8 + grp;
            unsigned bh0 = hcH[kpb * HPW + n];
            unsigned bh1 = hcH[(kpb + 4) * HPW + n];
            unsigned bm0 = hcM[kpb * HPW + n];
            unsigned bm1 = hcM[(kpb + 4) * HPW + n];
            mma16816(acc[nt], AH.x, AH.y, AH.z, AH.w, bh0, bh1);
            mma16816(acc[nt], AM.x, AM.y, AM.z, AM.w, bh0, bh1);
            mma16816(acc[nt], AH.x, AH.y, AH.z, AH.w, bm0, bm1);
        }
    }
}

__global__ __launch_bounds__(256, 1) void scan_mma_kernel(
    const float* __restrict__ Wfr, const float* __restrict__ Wbr,
    float* __restrict__ out)
{
    extern __shared__ unsigned usmem[];
    unsigned* Wpack = usmem;                     // fragment-packed bf16x2 hi/mid
    unsigned* hs = usmem + WPK_TOTAL;            // [4][2 plane][64 kpair][HPW]
    float* zx  = (float*)(usmem + WPK_TOTAL + 4 * CHUNKW);  // [2][32][64]
    float* zbuf = (float*)(usmem + WPK_TOTAL);   // alias: chunk buffer 0

    const int tx = threadIdx.x;
    const int cta = blockIdx.x;        // 0..127
    const int dir = cta >> 6;
    const int ci = cta & 63;           // index within direction
    const int hbase = ci * 8;
    const float* __restrict__ Wr = dir ? Wbr : Wfr;

    // Pre-split + fragment-pack resident Wr slice as bf16x2 words.
    for (int e = tx; e < WPK_TERM; e += 256) {
        int j = e & 3;
        int lane_ = (e >> 2) & 31;
        int kstep = (e >> 7) & 31;
        int wmi = e >> 12;
        int g_ = lane_ >> 2, t_ = lane_ & 3;
        int m = wmi * 16 + g_ + ((j & 1) ? 8 : 0);
        int kb = kstep * 16 + 2 * t_ + ((j & 2) ? 8 : 0);
        int gate = m >> 3, jc = m & 7;
        float w0 = Wr[(size_t)kb * G4 + gate * HH + hbase + jc];
        float w1 = Wr[(size_t)(kb + 1) * G4 + gate * HH + hbase + jc];
        unsigned p0 = bf16_split_pack(w0);   // (mid<<16)|hi
        unsigned p1 = bf16_split_pack(w1);
        Wpack[e] = prmt(p0, p1, 0x5410);                // hi word {hi0,hi1}
        Wpack[WPK_TERM + e] = prmt(p0, p1, 0x7632);     // mid word {mid0,mid1}
    }

    // Zero our slice of h plane buffer 0 (4 kpairs x 64 b x 2 planes)
    for (int idx = tx; idx < 512; idx += 256) {
        int pl = idx >> 8;
        int r = idx & 255;
        int kp = (hbase >> 1) + (r >> 6);
        int b = r & 63;
        g_hpl[0][dir][pl][kp][b] = 0u;
    }

    // Warp layout for MMA
    const int lane = tx & 31;
    const int warp = tx >> 5;
    const int wm = warp >> 2;          // 0..1, m0 = wm*16
    const int n0 = (warp & 3) * 16;    // n (batch) base
    const int grp = lane >> 2;         // 0..7
    const int tig = lane & 3;          // 0..3

    // Gate-phase mapping: thread owns adjacent pair (hj0, hj0+1) for batch b_p
    const int b_p = tx & 63;
    const int hj0 = (tx >> 6) * 2;     // 0,2,4,6
    const int hj1 = hj0 + 1;
    float c_reg0 = 0.f, c_reg1 = 0.f;

    const unsigned hs_addr = (unsigned)__cvta_generic_to_shared(hs);
    const unsigned zx_addr = (unsigned)__cvta_generic_to_shared(zx);

    float* out_sent = out + (size_t)Bsz * TT * (2 * HH);
    unsigned* cntp = &g_cnt2[dir][0];
    volatile unsigned* php = &g_phase2[dir][0];
    unsigned* flags = &g_flag[dir][0][0];

    // Init barrier (one-time heavyweight; phase 0 -> 1)
    __syncthreads();
    if (tx == 0) {
        __threadfence();
        unsigned old = atomicAdd(cntp, 1u);
        if (old == NCTA_DIR - 1) { *cntp = 0; __threadfence(); *php = 1; }
        else { while (*php < 1u) { } }
        __threadfence();
    }
    __syncthreads();

    // Prefetch zx[t=0] into buffer 0, drained immediately (keeps ladder clean)
    {
        const float* xzb = &g_xz[dir][dir ? (TT - 1) : 0][0][0];
        #pragma unroll
        for (int i = 0; i < 2; i++) {
            int s = tx + i * 256;
            int c = s >> 4, off = (s & 15) * 4;
            int gate = c >> 3, jj = c & 7;
            cp16(zx_addr + (c * 64 + off) * 4,
                 xzb + (size_t)(gate * HH + hbase + jj) * Bsz + off);
        }
        cp_commit();
        cp_wait<0>();
    }

    for (int t = 0; t < TT; t++) {
        const int rb = t & 1, wb = (t + 1) & 1;
        const int tq = dir ? (TT - 1 - t) : t;
        const int zb = t & 1;
        const unsigned target = (unsigned)(t + 1);
        const unsigned* hsrc = &g_hpl[rb][dir][0][0][0];   // [2 plane][256 kp][64]

        float acc[2][4];
        #pragma unroll
        for (int nt = 0; nt < 2; nt++)
            #pragma unroll
            for (int d = 0; d < 4; d++) acc[nt][d] = 0.f;

        // Interleaved producer-group polls, staging issues, and compute.
        if (t > 0) poll_group(flags, 0, tx, target);
        issue_chunk(hs_addr, hsrc, 0, tx);
        cp_commit();
        if (t > 0) poll_group(flags, 1, tx, target);
        issue_chunk(hs_addr, hsrc, 1, tx);
        cp_commit();

        cp_wait<1>();        // chunk 0 landed
        __syncthreads();
        compute_chunk(acc, hs, Wpack, 0, wm, lane, tig, grp, n0);

        if (t > 0) poll_group(flags, 2, tx, target);
        issue_chunk(hs_addr, hsrc, 2, tx);
        cp_commit();

        cp_wait<1>();        // chunk 1 landed
        __syncthreads();
        compute_chunk(acc, hs, Wpack, 1, wm, lane, tig, grp, n0);

        if (t > 0) poll_group(flags, 3, tx, target);
        issue_chunk(hs_addr, hsrc, 3, tx);
        if (t < TT - 1) {    // fold zx(t+1) prefetch into the last group
            const int tq2 = dir ? (TT - 2 - t) : (t + 1);
            const float* xzb = &g_xz[dir][tq2][0][0];
            unsigned zdst = zx_addr + ((t + 1) & 1) * 2048 * 4;
            #pragma unroll
            for (int i = 0; i < 2; i++) {
                int s = tx + i * 256;
                int c = s >> 4, off = (s & 15) * 4;
                int gate = c >> 3, jj = c & 7;
                cp16(zdst + (c * 64 + off) * 4,
                     xzb + (size_t)(gate * HH + hbase + jj) * Bsz + off);
            }
        }
        cp_commit();

        cp_wait<1>();        // chunk 2 landed
        __syncthreads();
        compute_chunk(acc, hs, Wpack, 2, wm, lane, tig, grp, n0);

        cp_wait<0>();        // chunk 3 + zx landed
        __syncthreads();
        compute_chunk(acc, hs, Wpack, 3, wm, lane, tig, grp, n0);

        // Write acc into zbuf[c][b]  (c = m index = gate*8+j); zbuf aliases
        // buffer 0, whose chunk-0 data is dead (all reads pre-chunk1 sync).
        {
            int m0 = wm * 16;
            #pragma unroll
            for (int nt = 0; nt < 2; nt++) {
                int n = n0 + nt * 8 + tig * 2;
                *(float2*)&zbuf[(m0 + grp) * 64 + n] =
                    make_float2(acc[nt][0], acc[nt][1]);
                *(float2*)&zbuf[(m0 + grp + 8) * 64 + n] =
                    make_float2(acc[nt][2], acc[nt][3]);
            }
        }
        __syncthreads();

        // Gate phase: (hj0, b_p) and (hj0+1, b_p)
        const float* zxc = zx + zb * 2048;
        float z0[4], z1[4];
        #pragma unroll
        for (int gate = 0; gate < 4; gate++) {
            int c0i = (gate * 8 + hj0) * 64 + b_p;
            int c1i = (gate * 8 + hj1) * 64 + b_p;
            z0[gate] = zxc[c0i] + zbuf[c0i];
            z1[gate] = zxc[c1i] + zbuf[c1i];
        }
        float i0 = sigf(z0[0]), f0 = sigf(z0[1]), g0 = tanhf(z0[2]), o0 = sigf(z0[3]);
        c_reg0 = f0 * c_reg0 + i0 * g0;
        float h0v = o0 * tanhf(c_reg0);
        float i1 = sigf(z1[0]), f1 = sigf(z1[1]), g1 = tanhf(z1[2]), o1 = sigf(z1[3]);
        c_reg1 = f1 * c_reg1 + i1 * g1;
        float h1v = o1 * tanhf(c_reg1);

        // Publish split h: adjacent (even,odd) pair -> one word per plane
        {
            unsigned p0 = bf16_split_pack(h0v);
            unsigned p1 = bf16_split_pack(h1v);
            int kp = (hbase >> 1) + (tx >> 6);
            g_hpl[wb][dir][0][kp][b_p] = prmt(p0, p1, 0x5410);  // hi plane word
            g_hpl[wb][dir][1][kp][b_p] = prmt(p0, p1, 0x7632);  // mid plane word
        }

        size_t wo = ((size_t)b_p * TT + tq) * (2 * HH) + dir * HH + hbase + hj0;
        if (t < TT - 1) {
            // ---- release-arrive: publishes (ordered by bar) then flag ----
            __syncthreads();
            if (tx == 0) st_release(&g_flag[dir][ci][0], (unsigned)(t + 2));
            *(float2*)(out + wo) = make_float2(h0v, h1v);
            // NO end-of-step poll: next iteration polls per producer group.
        } else {
            *(float2*)(out + wo) = make_float2(h0v, h1v);
            size_t so = (size_t)b_p * (2 * HH) + dir * HH + hbase + hj0;
            *(float2*)(out_sent + so) = make_float2(h0v, h1v);
        }
    }

    // ---- endgame: full heavyweight barrier (all polls done), then reset ----
    __syncthreads();
    if (tx == 0) {
        __threadfence();
        unsigned old = atomicAdd(cntp, 1u);
        if (old == NCTA_DIR - 1) { *cntp = 0; __threadfence(); *php = 2; }
        else { while (*php < 2u) { } }
        __threadfence();
        // safe now: every CTA has passed every flag poll
        g_flag[dir][ci][0] = 0u;
        __threadfence();
        unsigned old2 = atomicAdd(cntp, 1u);
        if (old2 == NCTA_DIR - 1) {      // last one restores barrier state
            *cntp = 0;
            __threadfence();
            *php = 0;
        }
    }
}

// ---------------------------------------------------------------------------
extern "C" void kernel_launch(void* const* d_in, const int* in_sizes, int n_in,
                              void* d_out, int out_size) {
    const float* x   = (const float*)d_in[0];
    const float* Wfk = (const float*)d_in[1];
    const float* Wfr = (const float*)d_in[2];
    const float* bf  = (const float*)d_in[3];
    const float* Wbk = (const float*)d_in[4];
    const float* Wbr = (const float*)d_in[5];
    const float* bb  = (const float*)d_in[6];
    float* out = (float*)d_out;

    cudaFuncSetAttribute(scan_mma_kernel,
                         cudaFuncAttributeMaxDynamicSharedMemorySize, SCAN_SMEM);
    cudaFuncSetAttribute(proj_mma_kernel,
                         cudaFuncAttributeMaxDynamicSharedMemorySize, PROJ_SMEM);

    dim3 pg(8, 256, 2);
    proj_mma_kernel<<<pg, 512, PROJ_SMEM>>>(x, Wfk, bf, Wbk, bb);
    scan_mma_kernel<<<NCTA, 256, SCAN_SMEM>>>(Wfr, Wbr, out);
}

// round 17
// speedup vs baseline: 1.7442x; 1.1429x over previous
#include <cuda_runtime.h>
#include <cuda_bf16.h>
#include <math.h>

#define Bsz 64
#define TT 512
#define DD 512
#define HH 512
#define G4 2048   // 4*H
#define NCTA 128
#define NCTA_DIR 64

// Scratch (static device globals are the sanctioned scratch mechanism)
__device__ float g_xz[2][TT][G4][Bsz];      // [dir][t][gatecol][b]  (512 MB)
// h state as separate hi/mid bf16 planes, kpair-packed:
// word [buf][dir][plane][kpair][b] = (bf16(k_even) | bf16(k_odd)<<16)
__device__ unsigned g_hpl[2][2][2][256][64];
__device__ unsigned g_cnt2[2][32];            // per-direction heavyweight barrier
__device__ volatile unsigned g_phase2[2][32];
__device__ unsigned g_flag[2][64][32];        // distributed step flags (128B stride)

// ---------------------------------------------------------------------------
// helpers
// ---------------------------------------------------------------------------
__device__ __forceinline__ unsigned f2tf(float f) {
    unsigned r;
    asm("cvt.rna.tf32.f32 %0, %1;" : "=r"(r) : "f"(f));
    return r;
}

__device__ __forceinline__ void mma1688(float c[4],
                                        unsigned a0, unsigned a1, unsigned a2, unsigned a3,
                                        unsigned b0, unsigned b1) {
    asm volatile(
        "mma.sync.aligned.m16n8k8.row.col.f32.tf32.tf32.f32 "
        "{%0,%1,%2,%3}, {%4,%5,%6,%7}, {%8,%9}, {%0,%1,%2,%3};\n"
        : "+f"(c[0]), "+f"(c[1]), "+f"(c[2]), "+f"(c[3])
        : "r"(a0), "r"(a1), "r"(a2), "r"(a3), "r"(b0), "r"(b1));
}

__device__ __forceinline__ void mma16816(float c[4],
                                         unsigned a0, unsigned a1, unsigned a2, unsigned a3,
                                         unsigned b0, unsigned b1) {
    asm volatile(
        "mma.sync.aligned.m16n8k16.row.col.f32.bf16.bf16.f32 "
        "{%0,%1,%2,%3}, {%4,%5,%6,%7}, {%8,%9}, {%0,%1,%2,%3};\n"
        : "+f"(c[0]), "+f"(c[1]), "+f"(c[2]), "+f"(c[3])
        : "r"(a0), "r"(a1), "r"(a2), "r"(a3), "r"(b0), "r"(b1));
}

__device__ __forceinline__ unsigned prmt(unsigned a, unsigned b, unsigned sel) {
    unsigned d;
    asm("prmt.b32 %0, %1, %2, %3;" : "=r"(d) : "r"(a), "r"(b), "r"(sel));
    return d;
}

__device__ __forceinline__ void cp16(unsigned saddr, const void* g) {
    asm volatile("cp.async.cg.shared.global [%0], [%1], 16;" :: "r"(saddr), "l"(g));
}
__device__ __forceinline__ void cp_commit() {
    asm volatile("cp.async.commit_group;");
}
template <int N>
__device__ __forceinline__ void cp_wait() {
    asm volatile("cp.async.wait_group %0;" :: "n"(N));
}

// bf16 split: w = hi + mid (+ eps); returns packed (mid<<16 | hi)
__device__ __forceinline__ unsigned bf16_split_pack(float w) {
    __nv_bfloat16 bh = __float2bfloat16(w);
    float mid = w - __bfloat162float(bh);
    __nv_bfloat16 bm = __float2bfloat16(mid);
    return ((unsigned)__bfloat16_as_ushort(bm) << 16) |
           (unsigned)__bfloat16_as_ushort(bh);
}

// release/acquire primitives
__device__ __forceinline__ void st_release(unsigned* p, unsigned v) {
    asm volatile("st.release.gpu.global.u32 [%0], %1;"
                 :: "l"(p), "r"(v) : "memory");
}
__device__ __forceinline__ unsigned ld_acquire(unsigned* p) {
    unsigned v;
    asm volatile("ld.acquire.gpu.global.u32 %0, [%1];"
                 : "=r"(v) : "l"(p) : "memory");
    return v;
}

// ---------------------------------------------------------------------------
// Kernel 1: input projection via tf32 tensor-core MMA (unchanged from R2).
// ---------------------------------------------------------------------------
#define W_PITCH 264
#define X_PITCH 36
#define W_ELEMS (32 * W_PITCH)
#define X_ELEMS (64 * X_PITCH)
#define PROJ_SMEM ((W_ELEMS + 2 * X_ELEMS) * 4)

__global__ __launch_bounds__(512, 1) void proj_mma_kernel(
    const float* __restrict__ x,
    const float* __restrict__ Wfk, const float* __restrict__ bf,
    const float* __restrict__ Wbk, const float* __restrict__ bb)
{
    extern __shared__ unsigned psm[];
    unsigned* w_s = psm;                 // [32][W_PITCH]  (k x col)
    unsigned* x_s = psm + W_ELEMS;       // [2][64][X_PITCH] (ts x b x k)

    const int tid = threadIdx.x;
    const int colTile = blockIdx.x;      // 0..7
    const int tpair = blockIdx.y;        // 0..255
    const int dir = blockIdx.z;          // 0..1
    const int colbase = colTile * 256;
    const float* __restrict__ Wk = dir ? Wbk : Wfk;
    const float* __restrict__ bias = dir ? bb : bf;

    const int lane = tid & 31;
    const int grp = lane >> 2;
    const int tig = lane & 3;
    const int wid = tid >> 5;
    const int wn = wid & 1;
    const int wm = wid >> 1;

    float acc[2][2][4][4];
    #pragma unroll
    for (int a = 0; a < 2; a++)
        #pragma unroll
        for (int b = 0; b < 2; b++)
            #pragma unroll
            for (int c = 0; c < 4; c++)
                #pragma unroll
                for (int d = 0; d < 4; d++) acc[a][b][c][d] = 0.f;

    #pragma unroll 1
    for (int k0 = 0; k0 < DD; k0 += 32) {
        __syncthreads();
        #pragma unroll
        for (int j = 0; j < 4; j++) {
            int e4 = tid + j * 512;
            int kk = e4 >> 6;
            int cc = (e4 & 63) * 4;
            float4 v = *(const float4*)(Wk + (size_t)(k0 + kk) * G4 + colbase + cc);
            uint4 u = make_uint4(f2tf(v.x), f2tf(v.y), f2tf(v.z), f2tf(v.w));
            *(uint4*)(w_s + kk * W_PITCH + cc) = u;
        }
        #pragma unroll
        for (int j = 0; j < 2; j++) {
            int f4 = tid + j * 512;
            int ts = f4 >> 9;
            int r = f4 & 511;
            int b = r >> 3;
            int kc4 = (r & 7) * 4;
            int t = tpair * 2 + ts;
            float4 v = *(const float4*)(x + ((size_t)b * TT + t) * DD + k0 + kc4);
            uint4 u = make_uint4(f2tf(v.x), f2tf(v.y), f2tf(v.z), f2tf(v.w));
            *(uint4*)(x_s + ts * X_ELEMS + b * X_PITCH + kc4) = u;
        }
        __syncthreads();

        #pragma unroll
        for (int ks = 0; ks < 4; ks++) {
            const int kr = ks * 8;
            unsigned a[2][4];
            #pragma unroll
            for (int mt = 0; mt < 2; mt++) {
                int cb = wm * 32 + mt * 16 + grp;
                a[mt][0] = w_s[(kr + tig) * W_PITCH + cb];
                a[mt][1] = w_s[(kr + tig) * W_PITCH + cb + 8];
                a[mt][2] = w_s[(kr + tig + 4) * W_PITCH + cb];
                a[mt][3] = w_s[(kr + tig + 4) * W_PITCH + cb + 8];
            }
            unsigned bb_[2][4][2];
            #pragma unroll
            for (int ts = 0; ts < 2; ts++)
                #pragma unroll
                for (int nt = 0; nt < 4; nt++) {
                    int idx = ts * X_ELEMS + (wn * 32 + nt * 8 + grp) * X_PITCH + kr + tig;
                    bb_[ts][nt][0] = x_s[idx];
                    bb_[ts][nt][1] = x_s[idx + 4];
                }
            #pragma unroll
            for (int ts = 0; ts < 2; ts++)
                #pragma unroll
                for (int mt = 0; mt < 2; mt++)
                    #pragma unroll
                    for (int nt = 0; nt < 4; nt++)
                        mma1688(acc[ts][mt][nt],
                                a[mt][0], a[mt][1], a[mt][2], a[mt][3],
                                bb_[ts][nt][0], bb_[ts][nt][1]);
        }
    }

    #pragma unroll
    for (int ts = 0; ts < 2; ts++) {
        int t = tpair * 2 + ts;
        float* gx = &g_xz[dir][t][0][0];
        #pragma unroll
        for (int mt = 0; mt < 2; mt++) {
            int col = colbase + wm * 32 + mt * 16 + grp;
            float bv = bias[col];
            float bv8 = bias[col + 8];
            #pragma unroll
            for (int nt = 0; nt < 4; nt++) {
                int b = wn * 32 + nt * 8 + tig * 2;
                float2 lo = make_float2(acc[ts][mt][nt][0] + bv,
                                        acc[ts][mt][nt][1] + bv);
                float2 hi = make_float2(acc[ts][mt][nt][2] + bv8,
                                        acc[ts][mt][nt][3] + bv8);
                *(float2*)(gx + (size_t)col * Bsz + b) = lo;
                *(float2*)(gx + (size_t)(col + 8) * Bsz + b) = hi;
            }
        }
    }
}

// ---------------------------------------------------------------------------
// Kernel 2: persistent bidirectional LSTM scan.
// R17 = R13 + 4 up-front chunk buffers (no mid-loop refill; zbuf aliases
// buffer 0) + R13's single end-of-step 64-flag poll (overlaps out store).
// ---------------------------------------------------------------------------
__device__ __forceinline__ float sigf(float v) { return 1.f / (1.f + __expf(-v)); }

// Wpack: [term(hi=0,mid=1)][wm(2)][kstep16(32)][lane(32)][4]  (uint32 words)
#define WPK_TERM (2 * 32 * 32 * 4)   // 8192 words per term
#define WPK_TOTAL (2 * WPK_TERM)     // 16384 words (64 KB)
#define HPW 72                       // words per kpair row (72 mod 32 == 8)
#define PLW (64 * HPW)               // 4608 words per plane per chunk
#define CHUNKW (2 * PLW)             // 9216 words per chunk buffer
// SMEM words: Wpack 16384, hs 4*9216 (zbuf aliases buf0), zx 2*2048 = 57344
#define SCAN_SMEM ((WPK_TOTAL + 4 * CHUNKW + 2 * 2048) * 4)   // 229376 B

__device__ __forceinline__ void issue_chunk(unsigned hs_addr,
                                            const unsigned* hsrc,
                                            int ch, int tx) {
    unsigned dstb = hs_addr + ch * CHUNKW * 4;
    #pragma unroll
    for (int i = 0; i < 8; i++) {
        int f4 = tx + i * 256;               // 0..2047
        int pl = f4 >> 10;                   // 0..1
        int kpl = (f4 >> 4) & 63;            // 0..63
        int b4 = (f4 & 15) * 4;              // 0..60
        cp16(dstb + (pl * PLW + kpl * HPW + b4) * 4,
             hsrc + pl * 16384 + (ch * 64 + kpl) * 64 + b4);
    }
}

__device__ __forceinline__ void compute_chunk(float acc[2][4],
                                              const unsigned* hs,
                                              const unsigned* Wpack,
                                              int ch, int wm, int lane,
                                              int tig, int grp, int n0) {
    const unsigned* hcH = hs + ch * CHUNKW;
    const unsigned* hcM = hcH + PLW;
    const unsigned* WH = Wpack + (wm * 32 + ch * 8) * 128;
    const unsigned* WM = WH + WPK_TERM;
    #pragma unroll
    for (int ks = 0; ks < 8; ks++) {
        uint4 AH = *(const uint4*)(WH + ks * 128 + lane * 4);
        uint4 AM = *(const uint4*)(WM + ks * 128 + lane * 4);
        const int kpb = ks * 8 + tig;
        #pragma unroll
        for (int nt = 0; nt < 2; nt++) {
            int n = n0 + nt * 8 + grp;
            unsigned bh0 = hcH[kpb * HPW + n];
            unsigned bh1 = hcH[(kpb + 4) * HPW + n];
            unsigned bm0 = hcM[kpb * HPW + n];
            unsigned bm1 = hcM[(kpb + 4) * HPW + n];
            mma16816(acc[nt], AH.x, AH.y, AH.z, AH.w, bh0, bh1);
            mma16816(acc[nt], AM.x, AM.y, AM.z, AM.w, bh0, bh1);
            mma16816(acc[nt], AH.x, AH.y, AH.z, AH.w, bm0, bm1);
        }
    }
}

__global__ __launch_bounds__(256, 1) void scan_mma_kernel(
    const float* __restrict__ Wfr, const float* __restrict__ Wbr,
    float* __restrict__ out)
{
    extern __shared__ unsigned usmem[];
    unsigned* Wpack = usmem;                     // fragment-packed bf16x2 hi/mid
    unsigned* hs = usmem + WPK_TOTAL;            // [4][2 plane][64 kpair][HPW]
    float* zx  = (float*)(usmem + WPK_TOTAL + 4 * CHUNKW);  // [2][32][64]
    float* zbuf = (float*)(usmem + WPK_TOTAL);   // alias: chunk buffer 0

    const int tx = threadIdx.x;
    const int cta = blockIdx.x;        // 0..127
    const int dir = cta >> 6;
    const int ci = cta & 63;           // index within direction
    const int hbase = ci * 8;
    const float* __restrict__ Wr = dir ? Wbr : Wfr;

    // Pre-split + fragment-pack resident Wr slice as bf16x2 words.
    for (int e = tx; e < WPK_TERM; e += 256) {
        int j = e & 3;
        int lane_ = (e >> 2) & 31;
        int kstep = (e >> 7) & 31;
        int wmi = e >> 12;
        int g_ = lane_ >> 2, t_ = lane_ & 3;
        int m = wmi * 16 + g_ + ((j & 1) ? 8 : 0);
        int kb = kstep * 16 + 2 * t_ + ((j & 2) ? 8 : 0);
        int gate = m >> 3, jc = m & 7;
        float w0 = Wr[(size_t)kb * G4 + gate * HH + hbase + jc];
        float w1 = Wr[(size_t)(kb + 1) * G4 + gate * HH + hbase + jc];
        unsigned p0 = bf16_split_pack(w0);   // (mid<<16)|hi
        unsigned p1 = bf16_split_pack(w1);
        Wpack[e] = prmt(p0, p1, 0x5410);                // hi word {hi0,hi1}
        Wpack[WPK_TERM + e] = prmt(p0, p1, 0x7632);     // mid word {mid0,mid1}
    }

    // Zero our slice of h plane buffer 0 (4 kpairs x 64 b x 2 planes)
    for (int idx = tx; idx < 512; idx += 256) {
        int pl = idx >> 8;
        int r = idx & 255;
        int kp = (hbase >> 1) + (r >> 6);
        int b = r & 63;
        g_hpl[0][dir][pl][kp][b] = 0u;
    }

    // Warp layout for MMA
    const int lane = tx & 31;
    const int warp = tx >> 5;
    const int wm = warp >> 2;          // 0..1, m0 = wm*16
    const int n0 = (warp & 3) * 16;    // n (batch) base
    const int grp = lane >> 2;         // 0..7
    const int tig = lane & 3;          // 0..3

    // Gate-phase mapping: thread owns adjacent pair (hj0, hj0+1) for batch b_p
    const int b_p = tx & 63;
    const int hj0 = (tx >> 6) * 2;     // 0,2,4,6
    const int hj1 = hj0 + 1;
    float c_reg0 = 0.f, c_reg1 = 0.f;

    const unsigned hs_addr = (unsigned)__cvta_generic_to_shared(hs);
    const unsigned zx_addr = (unsigned)__cvta_generic_to_shared(zx);

    float* out_sent = out + (size_t)Bsz * TT * (2 * HH);
    unsigned* cntp = &g_cnt2[dir][0];
    volatile unsigned* php = &g_phase2[dir][0];

    // Init barrier (one-time heavyweight; phase 0 -> 1)
    __syncthreads();
    if (tx == 0) {
        __threadfence();
        unsigned old = atomicAdd(cntp, 1u);
        if (old == NCTA_DIR - 1) { *cntp = 0; __threadfence(); *php = 1; }
        else { while (*php < 1u) { } }
        __threadfence();
    }
    __syncthreads();

    // Prefetch zx[t=0] into buffer 0, drained immediately (keeps ladder clean)
    {
        const float* xzb = &g_xz[dir][dir ? (TT - 1) : 0][0][0];
        #pragma unroll
        for (int i = 0; i < 2; i++) {
            int s = tx + i * 256;
            int c = s >> 4, off = (s & 15) * 4;
            int gate = c >> 3, jj = c & 7;
            cp16(zx_addr + (c * 64 + off) * 4,
                 xzb + (size_t)(gate * HH + hbase + jj) * Bsz + off);
        }
        cp_commit();
        cp_wait<0>();
    }

    for (int t = 0; t < TT; t++) {
        const int rb = t & 1, wb = (t + 1) & 1;
        const int tq = dir ? (TT - 1 - t) : t;
        const int zb = t & 1;
        const unsigned* hsrc = &g_hpl[rb][dir][0][0][0];   // [2 plane][256 kp][64]

        // Issue ALL FOUR chunks up front; zx(t+1) folds into the 4th group.
        issue_chunk(hs_addr, hsrc, 0, tx);
        cp_commit();
        issue_chunk(hs_addr, hsrc, 1, tx);
        cp_commit();
        issue_chunk(hs_addr, hsrc, 2, tx);
        cp_commit();
        issue_chunk(hs_addr, hsrc, 3, tx);
        if (t < TT - 1) {
            const int tq2 = dir ? (TT - 2 - t) : (t + 1);
            const float* xzb = &g_xz[dir][tq2][0][0];
            unsigned zdst = zx_addr + ((t + 1) & 1) * 2048 * 4;
            #pragma unroll
            for (int i = 0; i < 2; i++) {
                int s = tx + i * 256;
                int c = s >> 4, off = (s & 15) * 4;
                int gate = c >> 3, jj = c & 7;
                cp16(zdst + (c * 64 + off) * 4,
                     xzb + (size_t)(gate * HH + hbase + jj) * Bsz + off);
            }
        }
        cp_commit();

        float acc[2][4];
        #pragma unroll
        for (int nt = 0; nt < 2; nt++)
            #pragma unroll
            for (int d = 0; d < 4; d++) acc[nt][d] = 0.f;

        cp_wait<3>();        // chunk 0 landed
        __syncthreads();
        compute_chunk(acc, hs, Wpack, 0, wm, lane, tig, grp, n0);

        cp_wait<2>();        // chunk 1 landed
        __syncthreads();
        compute_chunk(acc, hs, Wpack, 1, wm, lane, tig, grp, n0);

        cp_wait<1>();        // chunk 2 landed
        __syncthreads();
        compute_chunk(acc, hs, Wpack, 2, wm, lane, tig, grp, n0);

        cp_wait<0>();        // chunk 3 + zx landed
        __syncthreads();
        compute_chunk(acc, hs, Wpack, 3, wm, lane, tig, grp, n0);

        // Write acc into zbuf[c][b]  (c = m index = gate*8+j); zbuf aliases
        // buffer 0, whose chunk-0 data is dead (reads ended 3 syncs ago).
        {
            int m0 = wm * 16;
            #pragma unroll
            for (int nt = 0; nt < 2; nt++) {
                int n = n0 + nt * 8 + tig * 2;
                *(float2*)&zbuf[(m0 + grp) * 64 + n] =
                    make_float2(acc[nt][0], acc[nt][1]);
                *(float2*)&zbuf[(m0 + grp + 8) * 64 + n] =
                    make_float2(acc[nt][2], acc[nt][3]);
            }
        }
        __syncthreads();

        // Gate phase: (hj0, b_p) and (hj0+1, b_p)
        const float* zxc = zx + zb * 2048;
        float z0[4], z1[4];
        #pragma unroll
        for (int gate = 0; gate < 4; gate++) {
            int c0i = (gate * 8 + hj0) * 64 + b_p;
            int c1i = (gate * 8 + hj1) * 64 + b_p;
            z0[gate] = zxc[c0i] + zbuf[c0i];
            z1[gate] = zxc[c1i] + zbuf[c1i];
        }
        float i0 = sigf(z0[0]), f0 = sigf(z0[1]), g0 = tanhf(z0[2]), o0 = sigf(z0[3]);
        c_reg0 = f0 * c_reg0 + i0 * g0;
        float h0v = o0 * tanhf(c_reg0);
        float i1 = sigf(z1[0]), f1 = sigf(z1[1]), g1 = tanhf(z1[2]), o1 = sigf(z1[3]);
        c_reg1 = f1 * c_reg1 + i1 * g1;
        float h1v = o1 * tanhf(c_reg1);

        // Publish split h: adjacent (even,odd) pair -> one word per plane
        {
            unsigned p0 = bf16_split_pack(h0v);
            unsigned p1 = bf16_split_pack(h1v);
            int kp = (hbase >> 1) + (tx >> 6);
            g_hpl[wb][dir][0][kp][b_p] = prmt(p0, p1, 0x5410);  // hi plane word
            g_hpl[wb][dir][1][kp][b_p] = prmt(p0, p1, 0x7632);  // mid plane word
        }

        size_t wo = ((size_t)b_p * TT + tq) * (2 * HH) + dir * HH + hbase + hj0;
        if (t < TT - 1) {
            // ---- distributed-flag arrive (release; cumulative over block) ----
            __syncthreads();
            if (tx == 0) st_release(&g_flag[dir][ci][0], (unsigned)(t + 2));
            // ---- output store overlaps the poll ----
            *(float2*)(out + wo) = make_float2(h0v, h1v);
            // ---- parallel poll: thread i watches flag slot i ----
            const unsigned target = (unsigned)(t + 2);
            int done;
            do {
                unsigned v = (tx < NCTA_DIR) ? ld_acquire(&g_flag[dir][tx][0])
                                             : target;
                done = __syncthreads_and((int)(v >= target));
            } while (!done);
        } else {
            *(float2*)(out + wo) = make_float2(h0v, h1v);
            size_t so = (size_t)b_p * (2 * HH) + dir * HH + hbase + hj0;
            *(float2*)(out_sent + so) = make_float2(h0v, h1v);
        }
    }

    // ---- endgame: full heavyweight barrier (all polls done), then reset ----
    __syncthreads();
    if (tx == 0) {
        __threadfence();
        unsigned old = atomicAdd(cntp, 1u);
        if (old == NCTA_DIR - 1) { *cntp = 0; __threadfence(); *php = 2; }
        else { while (*php < 2u) { } }
        __threadfence();
        // safe now: every CTA has passed every flag poll
        g_flag[dir][ci][0] = 0u;
        __threadfence();
        unsigned old2 = atomicAdd(cntp, 1u);
        if (old2 == NCTA_DIR - 1) {      // last one restores barrier state
            *cntp = 0;
            __threadfence();
            *php = 0;
        }
    }
}

// ---------------------------------------------------------------------------
extern "C" void kernel_launch(void* const* d_in, const int* in_sizes, int n_in,
                              void* d_out, int out_size) {
    const float* x   = (const float*)d_in[0];
    const float* Wfk = (const float*)d_in[1];
    const float* Wfr = (const float*)d_in[2];
    const float* bf  = (const float*)d_in[3];
    const float* Wbk = (const float*)d_in[4];
    const float* Wbr = (const float*)d_in[5];
    const float* bb  = (const float*)d_in[6];
    float* out = (float*)d_out;

    cudaFuncSetAttribute(scan_mma_kernel,
                         cudaFuncAttributeMaxDynamicSharedMemorySize, SCAN_SMEM);
    cudaFuncSetAttribute(proj_mma_kernel,
                         cudaFuncAttributeMaxDynamicSharedMemorySize, PROJ_SMEM);

    dim3 pg(8, 256, 2);
    proj_mma_kernel<<<pg, 512, PROJ_SMEM>>>(x, Wfk, bf, Wbk, bb);
    scan_mma_kernel<<<NCTA, 256, SCAN_SMEM>>>(Wfr, Wbr, out);
}